// round 15
// baseline (speedup 1.0000x reference)
#include <cuda_runtime.h>
#include <cuda_bf16.h>
#include <math.h>

// Problem constants (from reference): N=500000, E=16000000, IN_DIM=17
#define NMAX 500000
#define IN_DIM 17

// Fixed-point packing: per-edge encoded value = round(msg * 2^24) + 2^40.
// Accumulator = cnt*2^40 + sum_fixed, |sum_fixed| < 2^39 always.
#define FIX_SCALE 16777216.0f           // 2^24
#define FIX_INV   (1.0f / 16777216.0f)
#define CNT_SHIFT 40

// Scratch (allocation-free rule: __device__ globals)
__device__ __align__(16) unsigned long long g_accum[NMAX];  // {count, fixed sum}
__device__ __align__(16) float g_projl[NMAX];               // x @ w_l^T
__device__ __align__(16) float g_projr[NMAX];               // x @ w_r^T
__device__ int g_use64;                                     // edge_index is int64?

// ---------------------------------------------------------------------------
// Kernel 1: projections + accumulator zero + (block 0) dtype probe.
// x tile staged via cp.async.bulk (measured best of 4 variants: 11.7us;
// all variants sit at ~12us = short-kernel floor, so k_proj is DONE).
// ---------------------------------------------------------------------------
#define PROJ_TPB 256
#define TILE_FLOATS (PROJ_TPB * IN_DIM)         // 4352
#define TILE_BYTES  (TILE_FLOATS * 4)           // 17408

__device__ __forceinline__ unsigned smem_u32(const void* p) {
    unsigned a;
    asm("{ .reg .u64 t; cvta.to.shared.u64 t, %1; cvt.u32.u64 %0, t; }"
        : "=r"(a) : "l"(p));
    return a;
}

__global__ void k_proj(const float* __restrict__ x, long long total_bytes,
                       const float* __restrict__ wl,
                       const float* __restrict__ wr,
                       const long long* __restrict__ ei,
                       int n) {
    __shared__ __align__(128) float s_x[TILE_FLOATS];
    __shared__ __align__(8) unsigned long long s_mbar;

    long long base_bytes = (long long)blockIdx.x * TILE_BYTES;
    unsigned bytes = (unsigned)((total_bytes - base_bytes < TILE_BYTES)
                                    ? (total_bytes - base_bytes) : TILE_BYTES);

    unsigned mbar = smem_u32(&s_mbar);
    if (threadIdx.x == 0) {
        asm volatile("mbarrier.init.shared.b64 [%0], %1;"
                     :: "r"(mbar), "r"(1u) : "memory");
    }
    __syncthreads();
    if (threadIdx.x == 0) {
        asm volatile("mbarrier.arrive.expect_tx.shared.b64 _, [%0], %1;"
                     :: "r"(mbar), "r"(bytes) : "memory");
        asm volatile(
            "cp.async.bulk.shared::cta.global.mbarrier::complete_tx::bytes "
            "[%0], [%1], %2, [%3];"
            :: "r"(smem_u32(s_x)),
               "l"((const char*)x + base_bytes),
               "r"(bytes), "r"(mbar) : "memory");
    }

    // Overlap the dtype probe with the bulk copy (block 0, warp 0 only).
    // JAX without x64 silently downgrades the requested int64 edge_index to
    // int32; random int32 pairs read as int64 exceed [0,N) w.p. ~1.
    if (blockIdx.x == 0 && threadIdx.x < 32) {
        int bad = 0;
        for (int i = threadIdx.x; i < 2048; i += 32) {
            long long v = ei[i];
            if (v < 0 || v >= (long long)n) bad = 1;
        }
        bad = __any_sync(0xFFFFFFFFu, bad);
        if (threadIdx.x == 0) g_use64 = bad ? 0 : 1;
    }

    // Wait for the tile (phase 0).
    {
        unsigned done;
        do {
            asm volatile(
                "{\n\t.reg .pred p;\n\t"
                "mbarrier.try_wait.parity.shared.b64 p, [%1], %2;\n\t"
                "selp.b32 %0, 1, 0, p;\n\t}"
                : "=r"(done) : "r"(mbar), "r"(0u) : "memory");
        } while (!done);
    }

    int i = blockIdx.x * PROJ_TPB + threadIdx.x;
    if (i >= n) return;
    const float* xi = s_x + threadIdx.x * IN_DIM;
    float pl = 0.f, pr = 0.f;
#pragma unroll
    for (int k = 0; k < IN_DIM; k++) {
        float v = xi[k];
        pl = fmaf(v, __ldg(&wl[k]), pl);
        pr = fmaf(v, __ldg(&wr[k]), pr);
    }
    g_projl[i] = pl;
    g_projr[i] = pr;
    g_accum[i] = 0ULL;
}

// ---------------------------------------------------------------------------
// Kernel 2: edge scatter — NOW PERSISTENT GRID-STRIDE. The inner loop
// (8 edges/thread, front-batched gathers, one packed u64 RED per edge) is
// byte-identical to the 133.6us baseline; only the launch shape changed.
// Rationale: 7813 CTAs at ~6-8 CTAs/SM = ~9 waves; each wave transition
// costs ~2360 cyc + re-ramp (T_chip model) ~= 8-12us total. A persistent
// grid (SMs x occupancy CTAs, each looping with grid stride) removes them.
// Inner loop remains LTS-sector-bound (~1.1 GB L2 traffic, ~95% of cap).
// ---------------------------------------------------------------------------
#define EPT 8
#define EDGE_TPB 256

__device__ __forceinline__ void red_add_u64(unsigned long long* addr,
                                            unsigned long long v) {
    asm volatile("red.global.add.u64 [%0], %1;" :: "l"(addr), "l"(v) : "memory");
}

__device__ __forceinline__ unsigned long long pack_msg(float msg) {
    return (unsigned long long)(llrintf(msg * FIX_SCALE) + (1LL << CNT_SHIFT));
}

__global__ void __launch_bounds__(EDGE_TPB)
k_edge(const void* __restrict__ ei_raw, long long E, int n) {
    long long ngroups = (E + EPT - 1) / EPT;
    long long stride  = (long long)gridDim.x * EDGE_TPB;

    for (long long g = (long long)blockIdx.x * EDGE_TPB + threadIdx.x;
         g < ngroups; g += stride) {
        long long base = g * (long long)EPT;

        if (!g_use64) {
            // ---- int32 fast path (expected) ----
            const int* p = (const int*)ei_raw;
            if (base + EPT <= E) {
                int s[EPT], d[EPT];
#pragma unroll
                for (int j = 0; j < EPT; j += 4) {
                    int4 sv = __ldcs((const int4*)(p + base + j));
                    s[j] = sv.x; s[j + 1] = sv.y; s[j + 2] = sv.z; s[j + 3] = sv.w;
                }
#pragma unroll
                for (int j = 0; j < EPT; j += 4) {
                    int4 dv = __ldcs((const int4*)(p + E + base + j));
                    d[j] = dv.x; d[j + 1] = dv.y; d[j + 2] = dv.z; d[j + 3] = dv.w;
                }
                float m[EPT];
                bool ok[EPT];
#pragma unroll
                for (int j = 0; j < EPT; j++) {
                    ok[j] = (unsigned)s[j] < (unsigned)n && (unsigned)d[j] < (unsigned)n;
                    m[j] = ok[j] ? g_projl[s[j]] : 0.f;
                }
#pragma unroll
                for (int j = 0; j < EPT; j++)
                    if (ok[j]) red_add_u64(&g_accum[d[j]], pack_msg(m[j]));
            } else {
                int cnt = (int)(E - base);
                for (int j = 0; j < cnt; j++) {
                    int sj = __ldcs(p + base + j);
                    int dj = __ldcs(p + E + base + j);
                    if ((unsigned)sj < (unsigned)n && (unsigned)dj < (unsigned)n)
                        red_add_u64(&g_accum[dj], pack_msg(g_projl[sj]));
                }
            }
        } else {
            // ---- int64 path ----
            const long long* p = (const long long*)ei_raw;
            long long s[EPT], d[EPT];
            int cnt = (int)((base + EPT <= E) ? EPT : (E - base));
            if (cnt == EPT) {
#pragma unroll
                for (int j = 0; j < EPT; j += 2) {
                    longlong2 sv = __ldcs((const longlong2*)(p + base + j));
                    s[j] = sv.x; s[j + 1] = sv.y;
                }
#pragma unroll
                for (int j = 0; j < EPT; j += 2) {
                    longlong2 dv = __ldcs((const longlong2*)(p + E + base + j));
                    d[j] = dv.x; d[j + 1] = dv.y;
                }
            } else {
                for (int j = 0; j < cnt; j++) {
                    s[j] = __ldcs(p + base + j);
                    d[j] = __ldcs(p + E + base + j);
                }
            }
            float m[EPT];
            bool ok[EPT];
#pragma unroll
            for (int j = 0; j < EPT; j++) {
                ok[j] = (j < cnt) &&
                        (unsigned long long)s[j] < (unsigned long long)n &&
                        (unsigned long long)d[j] < (unsigned long long)n;
                m[j] = ok[j] ? g_projl[s[j]] : 0.f;
            }
#pragma unroll
            for (int j = 0; j < EPT; j++)
                if (ok[j]) red_add_u64(&g_accum[d[j]], pack_msg(m[j]));
        }
    }
}

// ---------------------------------------------------------------------------
// Kernel 3: finalize, 2 nodes/thread with vector loads.
// unpack -> mean -> lin_l + lin_r -> elu -> out linear.
// ---------------------------------------------------------------------------
__global__ void k_final(float* __restrict__ out,
                        const float* __restrict__ bl,
                        const float* __restrict__ wo,
                        const float* __restrict__ bo,
                        int n) {
    int i0 = 2 * (blockIdx.x * blockDim.x + threadIdx.x);
    if (i0 >= n) return;
    float BL = __ldg(&bl[0]), WO = __ldg(&wo[0]), BO = __ldg(&bo[0]);

    if (i0 + 1 < n) {
        ulonglong2 ac = *(const ulonglong2*)&g_accum[i0];
        float2 pr = *(const float2*)&g_projr[i0];
        float r[2];
        unsigned long long a[2] = {ac.x, ac.y};
        float prv[2] = {pr.x, pr.y};
#pragma unroll
        for (int j = 0; j < 2; j++) {
            long long c = (long long)((a[j] + (1ULL << (CNT_SHIFT - 1))) >> CNT_SHIFT);
            long long sumfix = (long long)a[j] - (c << CNT_SHIFT);
            float mean = ((float)sumfix * FIX_INV) / fmaxf((float)c, 1.0f);
            float h = mean + BL + prv[j];
            h = (h > 0.f) ? h : expm1f(h);
            r[j] = fmaf(h, WO, BO);
        }
        *(float2*)&out[i0] = make_float2(r[0], r[1]);
    } else {
        unsigned long long acc = g_accum[i0];
        long long c = (long long)((acc + (1ULL << (CNT_SHIFT - 1))) >> CNT_SHIFT);
        long long sumfix = (long long)acc - (c << CNT_SHIFT);
        float mean = ((float)sumfix * FIX_INV) / fmaxf((float)c, 1.0f);
        float h = mean + BL + g_projr[i0];
        h = (h > 0.f) ? h : expm1f(h);
        out[i0] = fmaf(h, WO, BO);
    }
}

// ---------------------------------------------------------------------------
// Inputs (metadata order): x[N*17] f32, edge_index[2*E] int (width probed),
// edge_weight[E] f32 (UNUSED, faithful to PyG SAGEConv), w_l[17], b_l[1],
// w_r[17], w_o[1], b_o[1]. Output: [N] f32.
// ---------------------------------------------------------------------------
extern "C" void kernel_launch(void* const* d_in, const int* in_sizes, int n_in,
                              void* d_out, int out_size) {
    const float* x  = (const float*)d_in[0];
    const void*  ei = d_in[1];
    const float* wl = (const float*)d_in[3];
    const float* bl = (const float*)d_in[4];
    const float* wr = (const float*)d_in[5];
    const float* wo = (const float*)d_in[6];
    const float* bo = (const float*)d_in[7];
    float* out = (float*)d_out;

    int       n = in_sizes[0] / IN_DIM;
    long long E = (long long)in_sizes[1] / 2;   // element count is dtype-invariant
    long long total_bytes = (long long)in_sizes[0] * 4;

    int pblocks = (n + PROJ_TPB - 1) / PROJ_TPB;
    k_proj<<<pblocks, PROJ_TPB>>>(x, total_bytes, wl, wr,
                                  (const long long*)ei, n);

    // Persistent grid: exactly one wave (SMs x achievable occupancy).
    static int edge_blocks = 0;              // computed once; deterministic
    if (edge_blocks == 0) {
        int sms = 0, occ = 0;
        cudaDeviceGetAttribute(&sms, cudaDevAttrMultiProcessorCount, 0);
        cudaOccupancyMaxActiveBlocksPerMultiprocessor(&occ, k_edge, EDGE_TPB, 0);
        if (sms <= 0) sms = 148;
        if (occ <= 0) occ = 6;
        edge_blocks = sms * occ;
    }
    long long ngroups = (E + EPT - 1) / EPT;
    long long maxblocks = (ngroups + EDGE_TPB - 1) / EDGE_TPB;
    int eblocks = (int)((maxblocks < (long long)edge_blocks) ? maxblocks
                                                             : edge_blocks);
    k_edge<<<eblocks, EDGE_TPB>>>(ei, E, n);

    const int TPB = 256;
    int fblocks = (n / 2 + TPB - 1) / TPB;
    k_final<<<fblocks, TPB>>>(out, bl, wo, bo, n);
}

// round 16
// speedup vs baseline: 1.1204x; 1.1204x over previous
#include <cuda_runtime.h>
#include <cuda_bf16.h>
#include <math.h>

// Problem constants (from reference): N=500000, E=16000000, IN_DIM=17
#define NMAX 500000
#define IN_DIM 17

// Fixed-point packing: per-edge encoded value = round(msg * 2^24) + 2^40.
// Accumulator = cnt*2^40 + sum_fixed, |sum_fixed| < 2^39 always.
#define FIX_SCALE 16777216.0f           // 2^24
#define FIX_INV   (1.0f / 16777216.0f)
#define CNT_SHIFT 40

// Scratch (allocation-free rule: __device__ globals)
__device__ __align__(16) unsigned long long g_accum[NMAX];  // {count, fixed sum}
__device__ __align__(16) float g_projl[NMAX];               // x @ w_l^T
__device__ __align__(16) float g_projr[NMAX];               // x @ w_r^T
__device__ int g_use64;                                     // edge_index is int64?

// ---------------------------------------------------------------------------
// Kernel 1: projections + accumulator zero + (block 0) dtype probe.
// x tile staged via cp.async.bulk (measured best of 4 variants: ~11.7us;
// all variants sit at ~12us = short-kernel floor => k_proj is DONE).
// ---------------------------------------------------------------------------
#define PROJ_TPB 256
#define TILE_FLOATS (PROJ_TPB * IN_DIM)         // 4352
#define TILE_BYTES  (TILE_FLOATS * 4)           // 17408

__device__ __forceinline__ unsigned smem_u32(const void* p) {
    unsigned a;
    asm("{ .reg .u64 t; cvta.to.shared.u64 t, %1; cvt.u32.u64 %0, t; }"
        : "=r"(a) : "l"(p));
    return a;
}

__global__ void k_proj(const float* __restrict__ x, long long total_bytes,
                       const float* __restrict__ wl,
                       const float* __restrict__ wr,
                       const long long* __restrict__ ei,
                       int n) {
    __shared__ __align__(128) float s_x[TILE_FLOATS];
    __shared__ __align__(8) unsigned long long s_mbar;

    long long base_bytes = (long long)blockIdx.x * TILE_BYTES;
    unsigned bytes = (unsigned)((total_bytes - base_bytes < TILE_BYTES)
                                    ? (total_bytes - base_bytes) : TILE_BYTES);

    unsigned mbar = smem_u32(&s_mbar);
    if (threadIdx.x == 0) {
        asm volatile("mbarrier.init.shared.b64 [%0], %1;"
                     :: "r"(mbar), "r"(1u) : "memory");
    }
    __syncthreads();
    if (threadIdx.x == 0) {
        asm volatile("mbarrier.arrive.expect_tx.shared.b64 _, [%0], %1;"
                     :: "r"(mbar), "r"(bytes) : "memory");
        asm volatile(
            "cp.async.bulk.shared::cta.global.mbarrier::complete_tx::bytes "
            "[%0], [%1], %2, [%3];"
            :: "r"(smem_u32(s_x)),
               "l"((const char*)x + base_bytes),
               "r"(bytes), "r"(mbar) : "memory");
    }

    // Overlap the dtype probe with the bulk copy (block 0, warp 0 only).
    // JAX without x64 silently downgrades the requested int64 edge_index to
    // int32; random int32 pairs read as int64 exceed [0,N) w.p. ~1.
    if (blockIdx.x == 0 && threadIdx.x < 32) {
        int bad = 0;
        for (int i = threadIdx.x; i < 2048; i += 32) {
            long long v = ei[i];
            if (v < 0 || v >= (long long)n) bad = 1;
        }
        bad = __any_sync(0xFFFFFFFFu, bad);
        if (threadIdx.x == 0) g_use64 = bad ? 0 : 1;
    }

    // Wait for the tile (phase 0).
    {
        unsigned done;
        do {
            asm volatile(
                "{\n\t.reg .pred p;\n\t"
                "mbarrier.try_wait.parity.shared.b64 p, [%1], %2;\n\t"
                "selp.b32 %0, 1, 0, p;\n\t}"
                : "=r"(done) : "r"(mbar), "r"(0u) : "memory");
        } while (!done);
    }

    int i = blockIdx.x * PROJ_TPB + threadIdx.x;
    if (i >= n) return;
    const float* xi = s_x + threadIdx.x * IN_DIM;   // stride 17: conflict-free
    float pl = 0.f, pr = 0.f;
#pragma unroll
    for (int k = 0; k < IN_DIM; k++) {
        float v = xi[k];
        pl = fmaf(v, __ldg(&wl[k]), pl);
        pr = fmaf(v, __ldg(&wr[k]), pr);
    }
    g_projl[i] = pl;
    g_projr[i] = pr;
    g_accum[i] = 0ULL;
}

// ---------------------------------------------------------------------------
// Kernel 2: edge scatter. FROZEN at the measured optimum:
//   - EPT=8, flat 7813-CTA launch (EPT=16 and persistent-grid BOTH regressed:
//     this kernel needs MANY small CTAs in flight for latency hiding)
//   - front-batched index loads + gathers (MLP), then 8 fire-and-forget
//     packed u64 REDs (fixed-point sum + count in one transaction)
//   - __ldcs keeps the 128 MB index stream out of L2 so the 2 MB gather
//     table + 4 MB accumulator stay resident
// Bound: LTS sector throughput (gather 16M + RED 16M 32B sectors ~ 1 GB of
// L2 traffic ~ 95% of chip cap).
// ---------------------------------------------------------------------------
#define EPT 8

__device__ __forceinline__ void red_add_u64(unsigned long long* addr,
                                            unsigned long long v) {
    asm volatile("red.global.add.u64 [%0], %1;" :: "l"(addr), "l"(v) : "memory");
}

__device__ __forceinline__ unsigned long long pack_msg(float msg) {
    return (unsigned long long)(llrintf(msg * FIX_SCALE) + (1LL << CNT_SHIFT));
}

__global__ void k_edge(const void* __restrict__ ei_raw, long long E, int n) {
    long long base = (long long)EPT * ((long long)blockIdx.x * blockDim.x + threadIdx.x);
    if (base >= E) return;

    if (!g_use64) {
        // ---- int32 fast path (expected) ----
        const int* p = (const int*)ei_raw;
        if (base + EPT <= E) {
            int s[EPT], d[EPT];
#pragma unroll
            for (int j = 0; j < EPT; j += 4) {
                int4 sv = __ldcs((const int4*)(p + base + j));
                s[j] = sv.x; s[j + 1] = sv.y; s[j + 2] = sv.z; s[j + 3] = sv.w;
            }
#pragma unroll
            for (int j = 0; j < EPT; j += 4) {
                int4 dv = __ldcs((const int4*)(p + E + base + j));
                d[j] = dv.x; d[j + 1] = dv.y; d[j + 2] = dv.z; d[j + 3] = dv.w;
            }
            float m[EPT];
            bool ok[EPT];
#pragma unroll
            for (int j = 0; j < EPT; j++) {
                ok[j] = (unsigned)s[j] < (unsigned)n && (unsigned)d[j] < (unsigned)n;
                m[j] = ok[j] ? g_projl[s[j]] : 0.f;
            }
#pragma unroll
            for (int j = 0; j < EPT; j++)
                if (ok[j]) red_add_u64(&g_accum[d[j]], pack_msg(m[j]));
        } else {
            int cnt = (int)(E - base);
            for (int j = 0; j < cnt; j++) {
                int sj = __ldcs(p + base + j);
                int dj = __ldcs(p + E + base + j);
                if ((unsigned)sj < (unsigned)n && (unsigned)dj < (unsigned)n)
                    red_add_u64(&g_accum[dj], pack_msg(g_projl[sj]));
            }
        }
    } else {
        // ---- int64 path ----
        const long long* p = (const long long*)ei_raw;
        long long s[EPT], d[EPT];
        int cnt = (int)((base + EPT <= E) ? EPT : (E - base));
        if (cnt == EPT) {
#pragma unroll
            for (int j = 0; j < EPT; j += 2) {
                longlong2 sv = __ldcs((const longlong2*)(p + base + j));
                s[j] = sv.x; s[j + 1] = sv.y;
            }
#pragma unroll
            for (int j = 0; j < EPT; j += 2) {
                longlong2 dv = __ldcs((const longlong2*)(p + E + base + j));
                d[j] = dv.x; d[j + 1] = dv.y;
            }
        } else {
            for (int j = 0; j < cnt; j++) {
                s[j] = __ldcs(p + base + j);
                d[j] = __ldcs(p + E + base + j);
            }
        }
        float m[EPT];
        bool ok[EPT];
#pragma unroll
        for (int j = 0; j < EPT; j++) {
            ok[j] = (j < cnt) &&
                    (unsigned long long)s[j] < (unsigned long long)n &&
                    (unsigned long long)d[j] < (unsigned long long)n;
            m[j] = ok[j] ? g_projl[s[j]] : 0.f;
        }
#pragma unroll
        for (int j = 0; j < EPT; j++)
            if (ok[j]) red_add_u64(&g_accum[d[j]], pack_msg(m[j]));
    }
}

// ---------------------------------------------------------------------------
// Kernel 3: finalize, 2 nodes/thread with vector loads.
// unpack -> mean -> lin_l + lin_r -> elu -> out linear.
// ---------------------------------------------------------------------------
__global__ void k_final(float* __restrict__ out,
                        const float* __restrict__ bl,
                        const float* __restrict__ wo,
                        const float* __restrict__ bo,
                        int n) {
    int i0 = 2 * (blockIdx.x * blockDim.x + threadIdx.x);
    if (i0 >= n) return;
    float BL = __ldg(&bl[0]), WO = __ldg(&wo[0]), BO = __ldg(&bo[0]);

    if (i0 + 1 < n) {
        ulonglong2 ac = *(const ulonglong2*)&g_accum[i0];
        float2 pr = *(const float2*)&g_projr[i0];
        float r[2];
        unsigned long long a[2] = {ac.x, ac.y};
        float prv[2] = {pr.x, pr.y};
#pragma unroll
        for (int j = 0; j < 2; j++) {
            long long c = (long long)((a[j] + (1ULL << (CNT_SHIFT - 1))) >> CNT_SHIFT);
            long long sumfix = (long long)a[j] - (c << CNT_SHIFT);
            float mean = ((float)sumfix * FIX_INV) / fmaxf((float)c, 1.0f);
            float h = mean + BL + prv[j];
            h = (h > 0.f) ? h : expm1f(h);
            r[j] = fmaf(h, WO, BO);
        }
        *(float2*)&out[i0] = make_float2(r[0], r[1]);
    } else {
        unsigned long long acc = g_accum[i0];
        long long c = (long long)((acc + (1ULL << (CNT_SHIFT - 1))) >> CNT_SHIFT);
        long long sumfix = (long long)acc - (c << CNT_SHIFT);
        float mean = ((float)sumfix * FIX_INV) / fmaxf((float)c, 1.0f);
        float h = mean + BL + g_projr[i0];
        h = (h > 0.f) ? h : expm1f(h);
        out[i0] = fmaf(h, WO, BO);
    }
}

// ---------------------------------------------------------------------------
// Inputs (metadata order): x[N*17] f32, edge_index[2*E] int (width probed),
// edge_weight[E] f32 (UNUSED, faithful to PyG SAGEConv), w_l[17], b_l[1],
// w_r[17], w_o[1], b_o[1]. Output: [N] f32.
// ---------------------------------------------------------------------------
extern "C" void kernel_launch(void* const* d_in, const int* in_sizes, int n_in,
                              void* d_out, int out_size) {
    const float* x  = (const float*)d_in[0];
    const void*  ei = d_in[1];
    const float* wl = (const float*)d_in[3];
    const float* bl = (const float*)d_in[4];
    const float* wr = (const float*)d_in[5];
    const float* wo = (const float*)d_in[6];
    const float* bo = (const float*)d_in[7];
    float* out = (float*)d_out;

    int       n = in_sizes[0] / IN_DIM;
    long long E = (long long)in_sizes[1] / 2;   // element count is dtype-invariant
    long long total_bytes = (long long)in_sizes[0] * 4;

    int pblocks = (n + PROJ_TPB - 1) / PROJ_TPB;
    k_proj<<<pblocks, PROJ_TPB>>>(x, total_bytes, wl, wr,
                                  (const long long*)ei, n);

    const int TPB = 256;
    long long groups = (E + EPT - 1) / EPT;
    int eblocks = (int)((groups + TPB - 1) / TPB);
    k_edge<<<eblocks, TPB>>>(ei, E, n);

    int fblocks = (n / 2 + TPB - 1) / TPB;
    k_final<<<fblocks, TPB>>>(out, bl, wo, bo, n);
}